// round 7
// baseline (speedup 1.0000x reference)
#include <cuda_runtime.h>
#include <cuda_bf16.h>
#include <math.h>
#include <stdint.h>

// Shapes (fixed)
#define D_  1024
#define B_  128
#define T_  256

#define KSTAGE  64                   // k per smem stage (128B bf16 rows)
#define NSTAGES (D_ / KSTAGE)        // 16
#define STAGE_BYTES 32768            // AHI 8K | ALO 8K | BHI 8K | BLO 8K
#define NBUF 4
#define SMEM_DYN (NBUF * STAGE_BYTES)   // 128 KB, 1 CTA/SM

// Device scratch (allocation-free)
__device__ unsigned short g_WcThi[4 * D_ * D_];   // combined W^T hi  [n][k]
__device__ unsigned short g_WcTlo[4 * D_ * D_];
__device__ unsigned short g_W1Thi[4 * D_ * D_];   // step-1 W^T hi
__device__ unsigned short g_W1Tlo[4 * D_ * D_];
__device__ unsigned short g_hHi[2][B_ * D_];      // h split ping-pong
__device__ unsigned short g_hLo[2][B_ * D_];
__device__ float          g_zero[B_ * D_];        // h0 = 0 (never written)

// ---------------------------------------------------------------------------
// PTX helpers (plain sm_80+ features only)
// ---------------------------------------------------------------------------
__device__ __forceinline__ uint32_t s2u(const void* p) {
    uint32_t a;
    asm("{ .reg .u64 t; cvta.to.shared.u64 t, %1; cvt.u32.u64 %0, t; }"
        : "=r"(a) : "l"(p));
    return a;
}
__device__ __forceinline__ void cpasync16(uint32_t dst, const void* src) {
    asm volatile("cp.async.cg.shared.global [%0], [%1], 16;" :: "r"(dst), "l"(src));
}
__device__ __forceinline__ void cp_commit() {
    asm volatile("cp.async.commit_group;" ::: "memory");
}
template <int N> __device__ __forceinline__ void cp_wait() {
    asm volatile("cp.async.wait_group %0;" :: "n"(N) : "memory");
}
__device__ __forceinline__ void ldsm4(uint32_t* r, uint32_t addr) {
    asm volatile("ldmatrix.sync.aligned.m8n8.x4.shared.b16 {%0,%1,%2,%3}, [%4];"
        : "=r"(r[0]), "=r"(r[1]), "=r"(r[2]), "=r"(r[3]) : "r"(addr));
}
__device__ __forceinline__ void mma_bf16(float* c, const uint32_t* a,
                                         uint32_t b0, uint32_t b1) {
    asm volatile("mma.sync.aligned.m16n8k16.row.col.f32.bf16.bf16.f32 "
        "{%0,%1,%2,%3}, {%4,%5,%6,%7}, {%8,%9}, {%0,%1,%2,%3};"
        : "+f"(c[0]), "+f"(c[1]), "+f"(c[2]), "+f"(c[3])
        : "r"(a[0]), "r"(a[1]), "r"(a[2]), "r"(a[3]), "r"(b0), "r"(b1));
}
__device__ __forceinline__ uint32_t sw128(uint32_t off) {
    return off ^ ((off >> 3) & 0x70);
}

// ---------------------------------------------------------------------------
// Prologue: combined weights, transposed to [n][k] (n = 4*d + g),
// gates g: {Wz+Rz, Wr+Rr, Wh, Rh} (Wc)  /  {Wz, Wr, Wh, 0} (W1, for t=1).
// ---------------------------------------------------------------------------
__global__ void prep_weights(const float* __restrict__ Wk,
                             const float* __restrict__ Wr) {
    int i = blockIdx.x * blockDim.x + threadIdx.x;   // 4096 * 128 threads
    int n  = i >> 7;
    int k0 = (i & 127) * 8;
    int d = n >> 2, g = n & 3;
    long o = (long)n * D_ + k0;
    #pragma unroll
    for (int j = 0; j < 8; j++) {
        long src = (long)(k0 + j) * (3 * D_) + (long)g * D_ + d;
        float wc, w1;
        if (g == 3) {
            float rh = Wr[(long)(k0 + j) * (3 * D_) + 2 * D_ + d];
            wc = rh; w1 = 0.f;
        } else {
            float a = Wk[src];
            float b = Wr[src];
            w1 = a;
            wc = (g == 2) ? a : (a + b);
        }
        __nv_bfloat16 ch = __float2bfloat16(wc);
        __nv_bfloat16 cl = __float2bfloat16(wc - __bfloat162float(ch));
        __nv_bfloat16 oh = __float2bfloat16(w1);
        __nv_bfloat16 ol = __float2bfloat16(w1 - __bfloat162float(oh));
        g_WcThi[o + j] = __bfloat16_as_ushort(ch);
        g_WcTlo[o + j] = __bfloat16_as_ushort(cl);
        g_W1Thi[o + j] = __bfloat16_as_ushort(oh);
        g_W1Tlo[o + j] = __bfloat16_as_ushort(ol);
    }
}

// out[:,0,:] = x0 ; split x0 into h buffer 0
__global__ void prep_x0(const float* __restrict__ x, float* __restrict__ out) {
    int i = blockIdx.x * blockDim.x + threadIdx.x;   // B_*D_
    int b = i >> 10, d = i & (D_ - 1);
    float v = x[(long)b * D_ + d];
    out[(long)b * (T_ * D_) + d] = v;
    __nv_bfloat16 hi = __float2bfloat16(v);
    g_hHi[0][i] = __bfloat16_as_ushort(hi);
    g_hLo[0][i] = __bfloat16_as_ushort(__float2bfloat16(v - __bfloat162float(hi)));
}

// ---------------------------------------------------------------------------
// Stage loader: all 256 threads fill one 32KB stage (8 x 16B per thread).
// ---------------------------------------------------------------------------
__device__ __forceinline__ void load_stage(
    uint32_t st, int k0,
    const unsigned short* __restrict__ Ahi, const unsigned short* __restrict__ Alo,
    const unsigned short* __restrict__ Bhi, const unsigned short* __restrict__ Blo,
    int mrow0, int nrow0, int tid)
{
    #pragma unroll
    for (int t = 0; t < 2; t++) {
        int r   = t * 256 + tid;       // 512 16B-chunks per 8KB tile
        int row = r >> 3, ch = r & 7;
        uint32_t sw = sw128((uint32_t)(row * 128 + ch * 16));
        const long ko = (long)k0 + ch * 8;
        cpasync16(st +         sw, Ahi + (long)(mrow0 + row) * D_ + ko);
        cpasync16(st + 8192  + sw, Alo + (long)(mrow0 + row) * D_ + ko);
        cpasync16(st + 16384 + sw, Bhi + (long)(nrow0 + row) * D_ + ko);
        cpasync16(st + 24576 + sw, Blo + (long)(nrow0 + row) * D_ + ko);
    }
}

// ---------------------------------------------------------------------------
// One GRU step. C[128,4096] = (Ahi+Alo) @ (Bhi+Blo)^T via 3 bf16 HMMA splits.
// Grid: 128 CTAs = 64 n-tiles (N=64) x 2 m-halves (M=64). 256 threads:
// 8 warps = 2x2 position grid x 2 kq-groups (k-quarters of each stage),
// warp tile 32x32, shared 4-deep pipeline, one __syncthreads per stage,
// end-of-kernel split-k combine through smem, group-0 epilogue.
// ---------------------------------------------------------------------------
extern __shared__ char dsm[];

__global__ __launch_bounds__(256, 1)
void gru_step_mma(const unsigned short* __restrict__ Ahi,
                  const unsigned short* __restrict__ Alo,
                  const unsigned short* __restrict__ Whi,
                  const unsigned short* __restrict__ Wlo,
                  const float* __restrict__ bias,
                  const float* __restrict__ h_old, int h_stride,
                  float* __restrict__ out_t,
                  unsigned short* __restrict__ nhi,
                  unsigned short* __restrict__ nlo)
{
    const uint32_t sbase = s2u(dsm);
    const int tid  = threadIdx.x;
    const int wid  = tid >> 5, lane = tid & 31;
    const int wk   = wid >> 2;                      // kq-group 0/1
    const int wl   = wid & 3;
    const int wm   = wl & 1,  wn   = wl >> 1;       // position grid 2(m) x 2(n)
    const int nb   = blockIdx.x & 63;               // n-tile index
    const int mh   = blockIdx.x >> 6;               // m-half
    const int mrow0 = mh * 64;
    const int nrow0 = nb * 64;

    float acc[2][4][4];                             // [mt][nt(n8)][4]
    #pragma unroll
    for (int i = 0; i < 2; i++)
        #pragma unroll
        for (int j = 0; j < 4; j++)
            #pragma unroll
            for (int q = 0; q < 4; q++) acc[i][j][q] = 0.f;

    // per-lane ldmatrix geometry
    const int fr   = (lane & 7) + ((lane >> 3) & 1) * 8;  // row within 16
    const int fch  = (lane >> 4) * 16;                    // byte col half (k8)
    const uint32_t swz = (uint32_t)(lane & 7) << 4;       // SW128 row mask

    // Prime pipeline: stages 0..2
    load_stage(sbase,                   0,          Ahi, Alo, Whi, Wlo, mrow0, nrow0, tid); cp_commit();
    load_stage(sbase + STAGE_BYTES,     KSTAGE,     Ahi, Alo, Whi, Wlo, mrow0, nrow0, tid); cp_commit();
    load_stage(sbase + 2 * STAGE_BYTES, 2 * KSTAGE, Ahi, Alo, Whi, Wlo, mrow0, nrow0, tid); cp_commit();

    int buf = 0;
    for (int s = 0; s < NSTAGES; s++) {
        if (s <= NSTAGES - 3)      cp_wait<2>();
        else if (s == NSTAGES - 2) cp_wait<1>();
        else                       cp_wait<0>();
        __syncthreads();

        // refill the buffer freed at stage s-1 with stage s+3
        if (s + 3 < NSTAGES) {
            int nxt = buf + 3; if (nxt >= NBUF) nxt -= NBUF;
            load_stage(sbase + (uint32_t)nxt * STAGE_BYTES, (s + 3) * KSTAGE,
                       Ahi, Alo, Whi, Wlo, mrow0, nrow0, tid);
            cp_commit();
        }

        const uint32_t st = sbase + (uint32_t)buf * STAGE_BYTES;
        const uint32_t aHi = st, aLo = st + 8192, bHi = st + 16384, bLo = st + 24576;

        #pragma unroll
        for (int kqi = 0; kqi < 2; kqi++) {
            const int kq = wk * 2 + kqi;            // this group's k-quarter
            const uint32_t c = (uint32_t)(kq * 32 + fch) ^ swz;
            uint32_t ah[2][4], al[2][4], bh[2][4], bl[2][4];
            #pragma unroll
            for (int mt = 0; mt < 2; mt++) {
                uint32_t ro = (uint32_t)((wm * 32 + mt * 16 + fr) * 128) + c;
                ldsm4(ah[mt], aHi + ro);
                ldsm4(al[mt], aLo + ro);
            }
            #pragma unroll
            for (int np = 0; np < 2; np++) {
                uint32_t ro = (uint32_t)((wn * 32 + np * 16 + fr) * 128) + c;
                ldsm4(bh[np], bHi + ro);
                ldsm4(bl[np], bLo + ro);
            }
            #pragma unroll
            for (int mt = 0; mt < 2; mt++)
                #pragma unroll
                for (int nt = 0; nt < 4; nt++) {
                    const int np = nt >> 1, j = nt & 1;
                    mma_bf16(acc[mt][nt], ah[mt], bh[np][j], bh[np][j + 2]);
                    mma_bf16(acc[mt][nt], ah[mt], bl[np][j], bl[np][j + 2]);
                    mma_bf16(acc[mt][nt], al[mt], bh[np][j], bh[np][j + 2]);
                }
        }
        buf = buf + 1; if (buf == NBUF) buf = 0;
    }

    // Epilogue coordinates (needed for h_old prefetch)
    const int g     = lane >> 2;
    const int odd   = lane & 1;
    const int tg2   = (lane >> 1) & 1;
    const int dbase = nb * 16 + wn * 8;
    const int rowb  = mh * 64 + wm * 32 + g + odd * 8;

    // Prefetch h_old while the combine goes through smem (group 0 only)
    float hold[2][4];
    if (wk == 0) {
        #pragma unroll
        for (int mt = 0; mt < 2; mt++) {
            const int row = rowb + mt * 16;
            #pragma unroll
            for (int nt = 0; nt < 4; nt++)
                hold[mt][nt] = h_old[(long)row * h_stride + dbase + nt * 2 + tg2];
        }
    }

    // -------- kq-split combine: group 1 -> smem (buf 0, drained), add -----
    // Padded stride 68 words to spread banks. Tile 64x68 floats = 17.4KB.
    const uint32_t comb = sbase;
    if (wk == 1) {
        #pragma unroll
        for (int mt = 0; mt < 2; mt++)
            #pragma unroll
            for (int nt = 0; nt < 4; nt++) {
                int r0 = wm * 32 + mt * 16 + (lane >> 2);
                int c0 = wn * 32 + nt * 8 + 2 * (lane & 3);
                uint32_t ad = comb + (uint32_t)((r0 * 68 + c0) << 2);
                asm volatile("st.shared.v2.f32 [%0], {%1,%2};"
                             :: "r"(ad), "f"(acc[mt][nt][0]), "f"(acc[mt][nt][1]));
                asm volatile("st.shared.v2.f32 [%0], {%1,%2};"
                             :: "r"(ad + 8 * 68 * 4), "f"(acc[mt][nt][2]), "f"(acc[mt][nt][3]));
            }
    }
    __syncthreads();
    if (wk == 1) return;

    #pragma unroll
    for (int mt = 0; mt < 2; mt++)
        #pragma unroll
        for (int nt = 0; nt < 4; nt++) {
            int r0 = wm * 32 + mt * 16 + (lane >> 2);
            int c0 = wn * 32 + nt * 8 + 2 * (lane & 3);
            uint32_t ad = comb + (uint32_t)((r0 * 68 + c0) << 2);
            float p0, p1, p2, p3;
            asm volatile("ld.shared.v2.f32 {%0,%1}, [%2];"
                         : "=f"(p0), "=f"(p1) : "r"(ad));
            asm volatile("ld.shared.v2.f32 {%0,%1}, [%2];"
                         : "=f"(p2), "=f"(p3) : "r"(ad + 8 * 68 * 4));
            acc[mt][nt][0] += p0; acc[mt][nt][1] += p1;
            acc[mt][nt][2] += p2; acc[mt][nt][3] += p3;
        }

    // ---------------- GRU gate epilogue (group 0) ----------------
    #pragma unroll
    for (int mt = 0; mt < 2; mt++) {
        const int row = rowb + mt * 16;
        float* po = out_t + (long)row * (T_ * D_);
        unsigned short* phi = nhi + (long)row * D_;
        unsigned short* plo = nlo + (long)row * D_;
        #pragma unroll
        for (int nt = 0; nt < 4; nt++) {
            float* a = acc[mt][nt];
            float v0 = odd ? a[0] : a[2];
            float v1 = odd ? a[1] : a[3];
            float rx0 = __shfl_xor_sync(0xffffffffu, v0, 1);
            float rx1 = __shfl_xor_sync(0xffffffffu, v1, 1);
            float az, ar, ahv, agv;
            if (!odd) { az = a[0]; ar = a[1]; ahv = rx0;  agv = rx1;  }
            else      { az = rx0; ar = rx1;  ahv = a[2];  agv = a[3]; }
            const int d = dbase + nt * 2 + tg2;
            float z    = 1.f / (1.f + __expf(-(az + bias[d])));
            float rr   = 1.f / (1.f + __expf(-(ar + bias[D_ + d])));
            float cand = tanhf(ahv + bias[2 * D_ + d] + rr * agv);
            float h    = z * hold[mt][nt] + (1.f - z) * cand;
            po[d] = h;
            __nv_bfloat16 hb = __float2bfloat16(h);
            phi[d] = __bfloat16_as_ushort(hb);
            plo[d] = __bfloat16_as_ushort(
                __float2bfloat16(h - __bfloat162float(hb)));
        }
    }
}

// ---------------------------------------------------------------------------
extern "C" void kernel_launch(void* const* d_in, const int* in_sizes, int n_in,
                              void* d_out, int out_size) {
    const float* x    = (const float*)d_in[0];
    const float* Wk   = (const float*)d_in[1];
    const float* Wr   = (const float*)d_in[2];
    const float* bias = (const float*)d_in[3];
    float* out = (float*)d_out;

    unsigned short *WcHi, *WcLo, *W1Hi, *W1Lo, *hHi, *hLo;
    float* zero;
    cudaGetSymbolAddress((void**)&WcHi, g_WcThi);
    cudaGetSymbolAddress((void**)&WcLo, g_WcTlo);
    cudaGetSymbolAddress((void**)&W1Hi, g_W1Thi);
    cudaGetSymbolAddress((void**)&W1Lo, g_W1Tlo);
    cudaGetSymbolAddress((void**)&hHi,  g_hHi);
    cudaGetSymbolAddress((void**)&hLo,  g_hLo);
    cudaGetSymbolAddress((void**)&zero, g_zero);

    cudaFuncSetAttribute(gru_step_mma,
                         cudaFuncAttributeMaxDynamicSharedMemorySize, SMEM_DYN);

    prep_weights<<<(4 * D_ * 128) / 256, 256>>>(Wk, Wr);
    prep_x0<<<(B_ * D_) / 256, 256>>>(x, out);

    // t = 1: A = x0 split (buf 0), h_old = 0, weights W1 (Rh = 0)
    gru_step_mma<<<128, 256, SMEM_DYN>>>(
        hHi, hLo, W1Hi, W1Lo, bias, zero, D_,
        out + D_, hHi + (size_t)B_ * D_, hLo + (size_t)B_ * D_);

    // t = 2..T-1: A = h_{t-1} split, h_old = out[:, t-1, :]
    for (int t = 2; t < T_; t++) {
        int rp = (t - 1) & 1, wp = t & 1;
        gru_step_mma<<<128, 256, SMEM_DYN>>>(
            hHi + (size_t)rp * B_ * D_, hLo + (size_t)rp * B_ * D_,
            WcHi, WcLo, bias,
            out + (size_t)(t - 1) * D_, T_ * D_,
            out + (size_t)t * D_,
            hHi + (size_t)wp * B_ * D_, hLo + (size_t)wp * B_ * D_);
    }
}

// round 8
// speedup vs baseline: 1.0203x; 1.0203x over previous
#include <cuda_runtime.h>
#include <cuda_bf16.h>
#include <math.h>
#include <stdint.h>

// Shapes (fixed)
#define D_  1024
#define B_  128
#define T_  256

#define KSTAGE  64                   // k per smem stage (128B bf16 rows)
#define NSTAGES (D_ / KSTAGE)        // 16
#define STAGE_BYTES 32768            // AHI 8K | ALO 8K | BHI 8K | BLO 8K
#define NBUF 4
#define SMEM_DYN (NBUF * STAGE_BYTES)   // 128 KB -> 1 CTA/SM, grid co-resident

// Device scratch (allocation-free)
__device__ unsigned short g_WcThi[4 * D_ * D_];   // combined W^T hi  [n][k]
__device__ unsigned short g_WcTlo[4 * D_ * D_];
__device__ unsigned short g_W1Thi[4 * D_ * D_];   // step-1 W^T hi
__device__ unsigned short g_W1Tlo[4 * D_ * D_];
__device__ unsigned short g_hHi[2][B_ * D_];      // h split ping-pong
__device__ unsigned short g_hLo[2][B_ * D_];
__device__ unsigned       g_bar;                  // grid barrier counter

// ---------------------------------------------------------------------------
// PTX helpers (plain sm_80+ features only)
// ---------------------------------------------------------------------------
__device__ __forceinline__ uint32_t s2u(const void* p) {
    uint32_t a;
    asm("{ .reg .u64 t; cvta.to.shared.u64 t, %1; cvt.u32.u64 %0, t; }"
        : "=r"(a) : "l"(p));
    return a;
}
__device__ __forceinline__ void cpasync16(uint32_t dst, const void* src) {
    asm volatile("cp.async.cg.shared.global [%0], [%1], 16;" :: "r"(dst), "l"(src));
}
__device__ __forceinline__ void cp_commit() {
    asm volatile("cp.async.commit_group;" ::: "memory");
}
template <int N> __device__ __forceinline__ void cp_wait() {
    asm volatile("cp.async.wait_group %0;" :: "n"(N) : "memory");
}
__device__ __forceinline__ void ldsm4(uint32_t* r, uint32_t addr) {
    asm volatile("ldmatrix.sync.aligned.m8n8.x4.shared.b16 {%0,%1,%2,%3}, [%4];"
        : "=r"(r[0]), "=r"(r[1]), "=r"(r[2]), "=r"(r[3]) : "r"(addr));
}
__device__ __forceinline__ void mma_bf16(float* c, const uint32_t* a,
                                         uint32_t b0, uint32_t b1) {
    asm volatile("mma.sync.aligned.m16n8k16.row.col.f32.bf16.bf16.f32 "
        "{%0,%1,%2,%3}, {%4,%5,%6,%7}, {%8,%9}, {%0,%1,%2,%3};"
        : "+f"(c[0]), "+f"(c[1]), "+f"(c[2]), "+f"(c[3])
        : "r"(a[0]), "r"(a[1]), "r"(a[2]), "r"(a[3]), "r"(b0), "r"(b1));
}
__device__ __forceinline__ uint32_t sw128(uint32_t off) {
    return off ^ ((off >> 3) & 0x70);
}

// ---------------------------------------------------------------------------
// Prologue kernels
// ---------------------------------------------------------------------------
__global__ void prep_weights(const float* __restrict__ Wk,
                             const float* __restrict__ Wr) {
    int i = blockIdx.x * blockDim.x + threadIdx.x;   // 4096 * 128 threads
    int n  = i >> 7;
    int k0 = (i & 127) * 8;
    int d = n >> 2, g = n & 3;
    long o = (long)n * D_ + k0;
    #pragma unroll
    for (int j = 0; j < 8; j++) {
        long src = (long)(k0 + j) * (3 * D_) + (long)g * D_ + d;
        float wc, w1;
        if (g == 3) {
            float rh = Wr[(long)(k0 + j) * (3 * D_) + 2 * D_ + d];
            wc = rh; w1 = 0.f;
        } else {
            float a = Wk[src];
            float b = Wr[src];
            w1 = a;
            wc = (g == 2) ? a : (a + b);
        }
        __nv_bfloat16 ch = __float2bfloat16(wc);
        __nv_bfloat16 cl = __float2bfloat16(wc - __bfloat162float(ch));
        __nv_bfloat16 oh = __float2bfloat16(w1);
        __nv_bfloat16 ol = __float2bfloat16(w1 - __bfloat162float(oh));
        g_WcThi[o + j] = __bfloat16_as_ushort(ch);
        g_WcTlo[o + j] = __bfloat16_as_ushort(cl);
        g_W1Thi[o + j] = __bfloat16_as_ushort(oh);
        g_W1Tlo[o + j] = __bfloat16_as_ushort(ol);
    }
}

// out[:,0,:] = x0 ; split x0 into h buffer 0 ; reset the grid barrier
__global__ void prep_x0(const float* __restrict__ x, float* __restrict__ out) {
    int i = blockIdx.x * blockDim.x + threadIdx.x;   // B_*D_
    if (i == 0) g_bar = 0u;
    int b = i >> 10, d = i & (D_ - 1);
    float v = x[(long)b * D_ + d];
    out[(long)b * (T_ * D_) + d] = v;
    __nv_bfloat16 hi = __float2bfloat16(v);
    g_hHi[0][i] = __bfloat16_as_ushort(hi);
    g_hLo[0][i] = __bfloat16_as_ushort(__float2bfloat16(v - __bfloat162float(hi)));
}

// ---------------------------------------------------------------------------
// Split stage loaders (A part / B part; each its own cp.async group)
// ---------------------------------------------------------------------------
__device__ __forceinline__ void load_A(
    uint32_t st, int k0,
    const unsigned short* Ahi, const unsigned short* Alo, int mrow0, int tid)
{
    #pragma unroll
    for (int t = 0; t < 2; t++) {
        int r   = t * 256 + tid;
        int row = r >> 3, ch = r & 7;
        uint32_t sw = sw128((uint32_t)(row * 128 + ch * 16));
        const long ko = (long)k0 + ch * 8;
        cpasync16(st +        sw, Ahi + (long)(mrow0 + row) * D_ + ko);
        cpasync16(st + 8192 + sw, Alo + (long)(mrow0 + row) * D_ + ko);
    }
}
__device__ __forceinline__ void load_B(
    uint32_t st, int k0,
    const unsigned short* Bhi, const unsigned short* Blo, int nrow0, int tid)
{
    #pragma unroll
    for (int t = 0; t < 2; t++) {
        int r   = t * 256 + tid;
        int row = r >> 3, ch = r & 7;
        uint32_t sw = sw128((uint32_t)(row * 128 + ch * 16));
        const long ko = (long)k0 + ch * 8;
        cpasync16(st + 16384 + sw, Bhi + (long)(nrow0 + row) * D_ + ko);
        cpasync16(st + 24576 + sw, Blo + (long)(nrow0 + row) * D_ + ko);
    }
}

// ---------------------------------------------------------------------------
// Persistent GRU kernel: 255 steps, grid barrier between steps.
// Grid: 128 CTAs = 64 n-tiles (N=64) x 2 m-halves (M=64), 256 threads,
// 8 warps 4(m) x 2(n), warp tile 16x32 (R6 geometry).
// Next-step B tiles prefetched pre-barrier (weights step-invariant).
// ---------------------------------------------------------------------------
extern __shared__ char dsm[];

__global__ __launch_bounds__(256, 1)
void gru_persist(const unsigned short* __restrict__ WcHi,
                 const unsigned short* __restrict__ WcLo,
                 const unsigned short* __restrict__ W1Hi,
                 const unsigned short* __restrict__ W1Lo,
                 const float* __restrict__ bias,
                 float* __restrict__ out,
                 unsigned short* __restrict__ hHi,
                 unsigned short* __restrict__ hLo)
{
    const uint32_t sbase = s2u(dsm);
    const int tid  = threadIdx.x;
    const int wid  = tid >> 5, lane = tid & 31;
    const int wm   = wid & 3;                       // 4 m-warps
    const int wn   = wid >> 2;                      // 2 n-warps
    const int nb   = blockIdx.x & 63;
    const int mh   = blockIdx.x >> 6;
    const int mrow0 = mh * 64;
    const int nrow0 = nb * 64;

    // per-lane ldmatrix geometry
    const int fr   = (lane & 7) + ((lane >> 3) & 1) * 8;
    const int fch  = (lane >> 4) * 16;
    const uint32_t swz = (uint32_t)(lane & 7) << 4;

    // epilogue coordinates
    const int g     = lane >> 2;
    const int odd   = lane & 1;
    const int tg2   = (lane >> 1) & 1;
    const int dbase = nb * 16 + wn * 8;
    const int row   = mh * 64 + wm * 16 + g + odd * 8;

    const float bz = bias[dbase + tg2];          // loaded fresh per nt below
    (void)bz;

    // ---- prime for t = 1: A = x0 split (buf 0), B = W1 ----
    const unsigned short* Ahi = hHi;
    const unsigned short* Alo = hLo;
    const unsigned short* Bhi = W1Hi;
    const unsigned short* Blo = W1Lo;

    load_B(sbase,                   0,          Bhi, Blo, nrow0, tid); cp_commit();
    load_B(sbase + STAGE_BYTES,     KSTAGE,     Bhi, Blo, nrow0, tid); cp_commit();
    load_B(sbase + 2 * STAGE_BYTES, 2 * KSTAGE, Bhi, Blo, nrow0, tid); cp_commit();
    load_A(sbase,                   0,          Ahi, Alo, mrow0, tid); cp_commit();
    load_A(sbase + STAGE_BYTES,     KSTAGE,     Ahi, Alo, mrow0, tid); cp_commit();
    load_A(sbase + 2 * STAGE_BYTES, 2 * KSTAGE, Ahi, Alo, mrow0, tid); cp_commit();

    float hold[4] = {0.f, 0.f, 0.f, 0.f};        // h0 = 0

    for (int t = 1; t < T_; t++) {
        const bool last = (t == T_ - 1);

        float acc[4][4];
        #pragma unroll
        for (int j = 0; j < 4; j++)
            #pragma unroll
            for (int q = 0; q < 4; q++) acc[j][q] = 0.f;

        int buf = 0;
        for (int s = 0; s < NSTAGES; s++) {
            if (!last)                 cp_wait<2>();
            else if (s <= NSTAGES - 3) cp_wait<2>();
            else if (s == NSTAGES - 2) cp_wait<1>();
            else                       cp_wait<0>();
            __syncthreads();

            if (s + 3 < NSTAGES) {
                int nxt = buf + 3; if (nxt >= NBUF) nxt -= NBUF;
                uint32_t st = sbase + (uint32_t)nxt * STAGE_BYTES;
                load_A(st, (s + 3) * KSTAGE, Ahi, Alo, mrow0, tid);
                load_B(st, (s + 3) * KSTAGE, Bhi, Blo, nrow0, tid);
                cp_commit();
            } else if (!last) {
                // prefetch NEXT step's B for stages 0..2 into bufs 0..2
                int nxt = buf + 3; if (nxt >= NBUF) nxt -= NBUF;
                uint32_t st = sbase + (uint32_t)nxt * STAGE_BYTES;
                load_B(st, (s - (NSTAGES - 3)) * KSTAGE, WcHi, WcLo, nrow0, tid);
                cp_commit();
            }

            const uint32_t st = sbase + (uint32_t)buf * STAGE_BYTES;
            const uint32_t aHi = st, aLo = st + 8192,
                           bHi = st + 16384, bLo = st + 24576;

            #pragma unroll
            for (int kq = 0; kq < 4; kq++) {
                const uint32_t c = (uint32_t)(kq * 32 + fch) ^ swz;
                uint32_t ah[4], al[4], bh[2][4], bl[2][4];
                {
                    uint32_t ro = (uint32_t)((wm * 16 + fr) * 128) + c;
                    ldsm4(ah, aHi + ro);
                    ldsm4(al, aLo + ro);
                }
                #pragma unroll
                for (int np = 0; np < 2; np++) {
                    uint32_t ro = (uint32_t)((wn * 32 + np * 16 + fr) * 128) + c;
                    ldsm4(bh[np], bHi + ro);
                    ldsm4(bl[np], bLo + ro);
                }
                #pragma unroll
                for (int nt = 0; nt < 4; nt++) {
                    const int np = nt >> 1, j = nt & 1;
                    mma_bf16(acc[nt], ah, bh[np][j], bh[np][j + 2]);
                    mma_bf16(acc[nt], ah, bl[np][j], bl[np][j + 2]);
                    mma_bf16(acc[nt], al, bh[np][j], bh[np][j + 2]);
                }
            }
            buf = buf + 1; if (buf == NBUF) buf = 0;
        }

        // ---------------- GRU gate epilogue ----------------
        unsigned short* nhi = hHi + (size_t)(t & 1) * B_ * D_;
        unsigned short* nlo = hLo + (size_t)(t & 1) * B_ * D_;
        {
            float* po = out + (long)row * (T_ * D_) + (long)t * D_;
            unsigned short* phi = nhi + (long)row * D_;
            unsigned short* plo = nlo + (long)row * D_;
            #pragma unroll
            for (int nt = 0; nt < 4; nt++) {
                float* a = acc[nt];
                float v0 = odd ? a[0] : a[2];
                float v1 = odd ? a[1] : a[3];
                float rx0 = __shfl_xor_sync(0xffffffffu, v0, 1);
                float rx1 = __shfl_xor_sync(0xffffffffu, v1, 1);
                float az, ar, ahv, agv;
                if (!odd) { az = a[0]; ar = a[1]; ahv = rx0;  agv = rx1;  }
                else      { az = rx0; ar = rx1;  ahv = a[2];  agv = a[3]; }
                const int d = dbase + nt * 2 + tg2;
                float z    = 1.f / (1.f + __expf(-(az + bias[d])));
                float rr   = 1.f / (1.f + __expf(-(ar + bias[D_ + d])));
                float cand = tanhf(ahv + bias[2 * D_ + d] + rr * agv);
                float h    = z * hold[nt] + (1.f - z) * cand;
                po[d] = h;
                __nv_bfloat16 hb = __float2bfloat16(h);
                phi[d] = __bfloat16_as_ushort(hb);
                plo[d] = __bfloat16_as_ushort(
                    __float2bfloat16(h - __bfloat162float(hb)));
            }
        }

        if (!last) {
            // ---- grid barrier: all h_t writes visible before step t+1 ----
            __threadfence();
            __syncthreads();
            if (tid == 0) {
                atomicAdd(&g_bar, 1u);
                volatile unsigned* vb = &g_bar;
                const unsigned target = 128u * (unsigned)t;
                while (*vb < target) { }
            }
            __syncthreads();
            __threadfence();

            // next step pointers
            Ahi = nhi; Alo = nlo;
            Bhi = WcHi; Blo = WcLo;

            // A loads for next step's stages 0..2 (bufs 0..2, B already there)
            load_A(sbase,                   0,          Ahi, Alo, mrow0, tid); cp_commit();
            load_A(sbase + STAGE_BYTES,     KSTAGE,     Ahi, Alo, mrow0, tid); cp_commit();
            load_A(sbase + 2 * STAGE_BYTES, 2 * KSTAGE, Ahi, Alo, mrow0, tid); cp_commit();

            // prefetch h_old (= h_t just produced) for next epilogue
            const float* hsrc = out + (long)t * D_ + (long)row * (T_ * D_);
            #pragma unroll
            for (int nt = 0; nt < 4; nt++)
                hold[nt] = hsrc[dbase + nt * 2 + tg2];
        }
    }
}

// ---------------------------------------------------------------------------
extern "C" void kernel_launch(void* const* d_in, const int* in_sizes, int n_in,
                              void* d_out, int out_size) {
    const float* x    = (const float*)d_in[0];
    const float* Wk   = (const float*)d_in[1];
    const float* Wr   = (const float*)d_in[2];
    const float* bias = (const float*)d_in[3];
    float* out = (float*)d_out;

    unsigned short *WcHi, *WcLo, *W1Hi, *W1Lo, *hHi, *hLo;
    cudaGetSymbolAddress((void**)&WcHi, g_WcThi);
    cudaGetSymbolAddress((void**)&WcLo, g_WcTlo);
    cudaGetSymbolAddress((void**)&W1Hi, g_W1Thi);
    cudaGetSymbolAddress((void**)&W1Lo, g_W1Tlo);
    cudaGetSymbolAddress((void**)&hHi,  g_hHi);
    cudaGetSymbolAddress((void**)&hLo,  g_hLo);

    cudaFuncSetAttribute(gru_persist,
                         cudaFuncAttributeMaxDynamicSharedMemorySize, SMEM_DYN);

    prep_weights<<<(4 * D_ * 128) / 256, 256>>>(Wk, Wr);
    prep_x0<<<(B_ * D_) / 256, 256>>>(x, out);   // also resets g_bar

    gru_persist<<<128, 256, SMEM_DYN>>>(WcHi, WcLo, W1Hi, W1Lo,
                                        bias, out, hHi, hLo);
}

// round 9
// speedup vs baseline: 1.0479x; 1.0271x over previous
#include <cuda_runtime.h>
#include <cuda_bf16.h>
#include <math.h>
#include <stdint.h>

// Shapes (fixed)
#define D_  1024
#define B_  128
#define T_  256

#define KSTAGE  64                   // k per smem stage (128B bf16 rows)
#define NSTAGES (D_ / KSTAGE)        // 16
// Stage: AHI 8K | ALO 8K | BHI 4K | BLO 4K  (M=64, N=32)
#define STAGE_BYTES 24576
#define NBUF 4
#define SMEM_DYN (NBUF * STAGE_BYTES)   // 96 KB -> 2 CTAs/SM

#define NCTA 256                     // 128 n-tiles x 2 m-halves

// Device scratch (allocation-free)
__device__ unsigned short g_WcThi[4 * D_ * D_];   // combined W^T hi  [n][k]
__device__ unsigned short g_WcTlo[4 * D_ * D_];
__device__ unsigned short g_W1Thi[4 * D_ * D_];   // step-1 W^T hi
__device__ unsigned short g_W1Tlo[4 * D_ * D_];
__device__ unsigned short g_hHi[2][B_ * D_];      // h split ping-pong
__device__ unsigned short g_hLo[2][B_ * D_];
__device__ unsigned       g_bar;                  // grid barrier counter

// ---------------------------------------------------------------------------
// PTX helpers (plain sm_80+ features only)
// ---------------------------------------------------------------------------
__device__ __forceinline__ uint32_t s2u(const void* p) {
    uint32_t a;
    asm("{ .reg .u64 t; cvta.to.shared.u64 t, %1; cvt.u32.u64 %0, t; }"
        : "=r"(a) : "l"(p));
    return a;
}
__device__ __forceinline__ void cpasync16(uint32_t dst, const void* src) {
    asm volatile("cp.async.cg.shared.global [%0], [%1], 16;" :: "r"(dst), "l"(src));
}
__device__ __forceinline__ void cp_commit() {
    asm volatile("cp.async.commit_group;" ::: "memory");
}
template <int N> __device__ __forceinline__ void cp_wait() {
    asm volatile("cp.async.wait_group %0;" :: "n"(N) : "memory");
}
__device__ __forceinline__ void ldsm4(uint32_t* r, uint32_t addr) {
    asm volatile("ldmatrix.sync.aligned.m8n8.x4.shared.b16 {%0,%1,%2,%3}, [%4];"
        : "=r"(r[0]), "=r"(r[1]), "=r"(r[2]), "=r"(r[3]) : "r"(addr));
}
__device__ __forceinline__ void mma_bf16(float* c, const uint32_t* a,
                                         uint32_t b0, uint32_t b1) {
    asm volatile("mma.sync.aligned.m16n8k16.row.col.f32.bf16.bf16.f32 "
        "{%0,%1,%2,%3}, {%4,%5,%6,%7}, {%8,%9}, {%0,%1,%2,%3};"
        : "+f"(c[0]), "+f"(c[1]), "+f"(c[2]), "+f"(c[3])
        : "r"(a[0]), "r"(a[1]), "r"(a[2]), "r"(a[3]), "r"(b0), "r"(b1));
}
__device__ __forceinline__ uint32_t sw128(uint32_t off) {
    return off ^ ((off >> 3) & 0x70);
}

// ---------------------------------------------------------------------------
// Prologue kernels (unchanged, verified)
// ---------------------------------------------------------------------------
__global__ void prep_weights(const float* __restrict__ Wk,
                             const float* __restrict__ Wr) {
    int i = blockIdx.x * blockDim.x + threadIdx.x;   // 4096 * 128 threads
    int n  = i >> 7;
    int k0 = (i & 127) * 8;
    int d = n >> 2, g = n & 3;
    long o = (long)n * D_ + k0;
    #pragma unroll
    for (int j = 0; j < 8; j++) {
        long src = (long)(k0 + j) * (3 * D_) + (long)g * D_ + d;
        float wc, w1;
        if (g == 3) {
            float rh = Wr[(long)(k0 + j) * (3 * D_) + 2 * D_ + d];
            wc = rh; w1 = 0.f;
        } else {
            float a = Wk[src];
            float b = Wr[src];
            w1 = a;
            wc = (g == 2) ? a : (a + b);
        }
        __nv_bfloat16 ch = __float2bfloat16(wc);
        __nv_bfloat16 cl = __float2bfloat16(wc - __bfloat162float(ch));
        __nv_bfloat16 oh = __float2bfloat16(w1);
        __nv_bfloat16 ol = __float2bfloat16(w1 - __bfloat162float(oh));
        g_WcThi[o + j] = __bfloat16_as_ushort(ch);
        g_WcTlo[o + j] = __bfloat16_as_ushort(cl);
        g_W1Thi[o + j] = __bfloat16_as_ushort(oh);
        g_W1Tlo[o + j] = __bfloat16_as_ushort(ol);
    }
}

// out[:,0,:] = x0 ; split x0 into h buffer 0 ; reset the grid barrier
__global__ void prep_x0(const float* __restrict__ x, float* __restrict__ out) {
    int i = blockIdx.x * blockDim.x + threadIdx.x;   // B_*D_
    if (i == 0) g_bar = 0u;
    int b = i >> 10, d = i & (D_ - 1);
    float v = x[(long)b * D_ + d];
    out[(long)b * (T_ * D_) + d] = v;
    __nv_bfloat16 hi = __float2bfloat16(v);
    g_hHi[0][i] = __bfloat16_as_ushort(hi);
    g_hLo[0][i] = __bfloat16_as_ushort(__float2bfloat16(v - __bfloat162float(hi)));
}

// ---------------------------------------------------------------------------
// Stage loaders. A: 64 rows x 64 k (hi+lo 16KB). B: 32 rows x 64 k (8KB).
// ---------------------------------------------------------------------------
__device__ __forceinline__ void load_A(
    uint32_t st, int k0,
    const unsigned short* Ahi, const unsigned short* Alo, int mrow0, int tid)
{
    #pragma unroll
    for (int t = 0; t < 2; t++) {
        int r   = t * 256 + tid;               // 512 chunks per 8KB tile
        int row = r >> 3, ch = r & 7;
        uint32_t sw = sw128((uint32_t)(row * 128 + ch * 16));
        const long ko = (long)k0 + ch * 8;
        cpasync16(st +        sw, Ahi + (long)(mrow0 + row) * D_ + ko);
        cpasync16(st + 8192 + sw, Alo + (long)(mrow0 + row) * D_ + ko);
    }
}
__device__ __forceinline__ void load_B(
    uint32_t st, int k0,
    const unsigned short* Bhi, const unsigned short* Blo, int nrow0, int tid)
{
    int row = tid >> 3, ch = tid & 7;          // 256 chunks per 4KB tile
    uint32_t sw = sw128((uint32_t)(row * 128 + ch * 16));
    const long ko = (long)k0 + ch * 8;
    cpasync16(st + 16384 + sw, Bhi + (long)(nrow0 + row) * D_ + ko);
    cpasync16(st + 20480 + sw, Blo + (long)(nrow0 + row) * D_ + ko);
}

// ---------------------------------------------------------------------------
// Persistent GRU kernel: 255 steps, grid barrier between steps.
// Grid: 256 CTAs = 128 n-tiles (N=32) x 2 m-halves (M=64); 2 CTAs/SM.
// 256 threads, 8 warps 4(m) x 2(n), warp tile 16x16.
// Next-step B tiles prefetched pre-barrier (weights step-invariant);
// h_old carried in registers across the barrier.
// ---------------------------------------------------------------------------
extern __shared__ char dsm[];

__global__ __launch_bounds__(256, 2)
void gru_persist(const unsigned short* __restrict__ WcHi,
                 const unsigned short* __restrict__ WcLo,
                 const unsigned short* __restrict__ W1Hi,
                 const unsigned short* __restrict__ W1Lo,
                 const float* __restrict__ bias,
                 float* __restrict__ out,
                 unsigned short* __restrict__ hHi,
                 unsigned short* __restrict__ hLo)
{
    const uint32_t sbase = s2u(dsm);
    const int tid  = threadIdx.x;
    const int wid  = tid >> 5, lane = tid & 31;
    const int wm   = wid & 3;                       // 4 m-warps (16 rows each)
    const int wn   = wid >> 2;                      // 2 n-warps (16 cols each)
    const int nb   = blockIdx.x & 127;              // 128 n-tiles
    const int mh   = blockIdx.x >> 7;               // 2 m-halves
    const int mrow0 = mh * 64;
    const int nrow0 = nb * 32;

    // per-lane ldmatrix geometry
    const int fr   = (lane & 7) + ((lane >> 3) & 1) * 8;
    const int fch  = (lane >> 4) * 16;
    const uint32_t swz = (uint32_t)(lane & 7) << 4;

    // epilogue coordinates (static across steps)
    const int g     = lane >> 2;
    const int odd   = lane & 1;
    const int tg2   = (lane >> 1) & 1;
    const int dbase = nb * 8 + wn * 4;
    const int row   = mh * 64 + wm * 16 + g + odd * 8;

    // bias registers (d mapping is static)
    float bzv[2], brv[2], bhv[2];
    #pragma unroll
    for (int nt = 0; nt < 2; nt++) {
        const int d = dbase + nt * 2 + tg2;
        bzv[nt] = bias[d];
        brv[nt] = bias[D_ + d];
        bhv[nt] = bias[2 * D_ + d];
    }

    // ---- prime for t = 1: A = x0 split (buf 0..2), B = W1 ----
    const unsigned short* Ahi = hHi;
    const unsigned short* Alo = hLo;
    const unsigned short* Bhi = W1Hi;
    const unsigned short* Blo = W1Lo;

    #pragma unroll
    for (int s = 0; s < 3; s++) {
        uint32_t st = sbase + (uint32_t)s * STAGE_BYTES;
        load_B(st, s * KSTAGE, Bhi, Blo, nrow0, tid);
        load_A(st, s * KSTAGE, Ahi, Alo, mrow0, tid);
        cp_commit();
    }

    float hold[2] = {0.f, 0.f};                  // h0 = 0

    for (int t = 1; t < T_; t++) {
        const bool last = (t == T_ - 1);

        float acc[2][4];
        #pragma unroll
        for (int j = 0; j < 2; j++)
            #pragma unroll
            for (int q = 0; q < 4; q++) acc[j][q] = 0.f;

        int buf = 0;
        for (int s = 0; s < NSTAGES; s++) {
            if (!last)                 cp_wait<2>();
            else if (s <= NSTAGES - 3) cp_wait<2>();
            else if (s == NSTAGES - 2) cp_wait<1>();
            else                       cp_wait<0>();
            __syncthreads();

            if (s + 3 < NSTAGES) {
                int nxt = buf + 3; if (nxt >= NBUF) nxt -= NBUF;
                uint32_t st = sbase + (uint32_t)nxt * STAGE_BYTES;
                load_B(st, (s + 3) * KSTAGE, Bhi, Blo, nrow0, tid);
                load_A(st, (s + 3) * KSTAGE, Ahi, Alo, mrow0, tid);
                cp_commit();
            } else if (!last) {
                // prefetch NEXT step's B for stages 0..2 into bufs 0..2
                int nxt = buf + 3; if (nxt >= NBUF) nxt -= NBUF;
                uint32_t st = sbase + (uint32_t)nxt * STAGE_BYTES;
                load_B(st, (s - (NSTAGES - 3)) * KSTAGE, WcHi, WcLo, nrow0, tid);
                cp_commit();
            }

            const uint32_t st = sbase + (uint32_t)buf * STAGE_BYTES;
            const uint32_t aHi = st, aLo = st + 8192,
                           bHi = st + 16384, bLo = st + 20480;

            #pragma unroll
            for (int kq = 0; kq < 4; kq++) {
                const uint32_t c = (uint32_t)(kq * 32 + fch) ^ swz;
                uint32_t ah[4], al[4], bh[4], bl[4];
                {
                    uint32_t ro = (uint32_t)((wm * 16 + fr) * 128) + c;
                    ldsm4(ah, aHi + ro);
                    ldsm4(al, aLo + ro);
                }
                {
                    uint32_t ro = (uint32_t)((wn * 16 + fr) * 128) + c;
                    ldsm4(bh, bHi + ro);
                    ldsm4(bl, bLo + ro);
                }
                #pragma unroll
                for (int nt = 0; nt < 2; nt++) {
                    mma_bf16(acc[nt], ah, bh[nt], bh[nt + 2]);
                    mma_bf16(acc[nt], ah, bl[nt], bl[nt + 2]);
                    mma_bf16(acc[nt], al, bh[nt], bh[nt + 2]);
                }
            }
            buf = buf + 1; if (buf == NBUF) buf = 0;
        }

        // ---------------- GRU gate epilogue ----------------
        unsigned short* nhi = hHi + (size_t)(t & 1) * B_ * D_;
        unsigned short* nlo = hLo + (size_t)(t & 1) * B_ * D_;
        {
            float* po = out + (long)row * (T_ * D_) + (long)t * D_;
            unsigned short* phi = nhi + (long)row * D_;
            unsigned short* plo = nlo + (long)row * D_;
            #pragma unroll
            for (int nt = 0; nt < 2; nt++) {
                float* a = acc[nt];
                float v0 = odd ? a[0] : a[2];
                float v1 = odd ? a[1] : a[3];
                float rx0 = __shfl_xor_sync(0xffffffffu, v0, 1);
                float rx1 = __shfl_xor_sync(0xffffffffu, v1, 1);
                float az, ar, ahv, agv;
                if (!odd) { az = a[0]; ar = a[1]; ahv = rx0;  agv = rx1;  }
                else      { az = rx0; ar = rx1;  ahv = a[2];  agv = a[3]; }
                const int d = dbase + nt * 2 + tg2;
                float z    = 1.f / (1.f + __expf(-(az + bzv[nt])));
                float rr   = 1.f / (1.f + __expf(-(ar + brv[nt])));
                float cand = tanhf(ahv + bhv[nt] + rr * agv);
                float h    = z * hold[nt] + (1.f - z) * cand;
                hold[nt] = h;                 // h_old for next step, in regs
                po[d] = h;
                __nv_bfloat16 hb = __float2bfloat16(h);
                phi[d] = __bfloat16_as_ushort(hb);
                plo[d] = __bfloat16_as_ushort(
                    __float2bfloat16(h - __bfloat162float(hb)));
            }
        }

        if (!last) {
            // ---- grid barrier: all h_t writes visible before step t+1 ----
            __threadfence();
            __syncthreads();
            if (tid == 0) {
                atomicAdd(&g_bar, 1u);
                volatile unsigned* vb = &g_bar;
                const unsigned target = (unsigned)NCTA * (unsigned)t;
                while (*vb < target) { }
            }
            __syncthreads();
            __threadfence();

            // next step pointers
            Ahi = nhi; Alo = nlo;
            Bhi = WcHi; Blo = WcLo;

            // A loads for next step's stages 0..2 (B already prefetched)
            load_A(sbase,                   0,          Ahi, Alo, mrow0, tid); cp_commit();
            load_A(sbase + STAGE_BYTES,     KSTAGE,     Ahi, Alo, mrow0, tid); cp_commit();
            load_A(sbase + 2 * STAGE_BYTES, 2 * KSTAGE, Ahi, Alo, mrow0, tid); cp_commit();
        }
    }
}

// ---------------------------------------------------------------------------
extern "C" void kernel_launch(void* const* d_in, const int* in_sizes, int n_in,
                              void* d_out, int out_size) {
    const float* x    = (const float*)d_in[0];
    const float* Wk   = (const float*)d_in[1];
    const float* Wr   = (const float*)d_in[2];
    const float* bias = (const float*)d_in[3];
    float* out = (float*)d_out;

    unsigned short *WcHi, *WcLo, *W1Hi, *W1Lo, *hHi, *hLo;
    cudaGetSymbolAddress((void**)&WcHi, g_WcThi);
    cudaGetSymbolAddress((void**)&WcLo, g_WcTlo);
    cudaGetSymbolAddress((void**)&W1Hi, g_W1Thi);
    cudaGetSymbolAddress((void**)&W1Lo, g_W1Tlo);
    cudaGetSymbolAddress((void**)&hHi,  g_hHi);
    cudaGetSymbolAddress((void**)&hLo,  g_hLo);

    cudaFuncSetAttribute(gru_persist,
                         cudaFuncAttributeMaxDynamicSharedMemorySize, SMEM_DYN);

    prep_weights<<<(4 * D_ * 128) / 256, 256>>>(Wk, Wr);
    prep_x0<<<(B_ * D_) / 256, 256>>>(x, out);   // also resets g_bar

    gru_persist<<<NCTA, 256, SMEM_DYN>>>(WcHi, WcLo, W1Hi, W1Lo,
                                         bias, out, hHi, hLo);
}